// round 2
// baseline (speedup 1.0000x reference)
#include <cuda_runtime.h>

#define NPIX (512*512)
#define D1B 6
#define D1S 3
#define MAXMB (D1B*NPIX+1)
#define MAXMS (D1S*NPIX+1)
#define ALPHA_B (32.0f/33.0f)
#define ALPHA_S 0.8f
#define BI_COMPAT 10.0f
#define SP_COMPAT 3.0f

// Scratch: tables (ping-pong), Q, per-pixel inverse norms. Device globals (no allocs allowed).
__device__ float4 g_tb[2][MAXMB];
__device__ float4 g_ts[2][MAXMS];
__device__ float4 g_Q[NPIX];
__device__ float  g_inb[NPIX];
__device__ float  g_ins[NPIX];

__device__ __forceinline__ void red4(float4* p, float x, float y, float z, float w) {
    asm volatile("red.global.add.v4.f32 [%0], {%1,%2,%3,%4};"
                 :: "l"(p), "f"(x), "f"(y), "f"(z), "f"(w) : "memory");
}

__device__ __forceinline__ float4 softmax_neg(float4 u, float4 msg) {
    // softmax over (-u + msg)
    float zx = msg.x - u.x, zy = msg.y - u.y, zz = msg.z - u.z, zw = msg.w - u.w;
    float m = fmaxf(fmaxf(zx, zy), fmaxf(zz, zw));
    float ex = __expf(zx - m), ey = __expf(zy - m), ez = __expf(zz - m), ew = __expf(zw - m);
    float inv = 1.0f / (ex + ey + ez + ew);
    return make_float4(ex * inv, ey * inv, ez * inv, ew * inv);
}

__global__ void __launch_bounds__(256) init_q(const float4* __restrict__ unary) {
    int n = blockIdx.x * blockDim.x + threadIdx.x;
    if (n >= NPIX) return;
    g_Q[n] = softmax_neg(unary[n], make_float4(0.f, 0.f, 0.f, 0.f));
}

__global__ void __launch_bounds__(256) zero_tables(int mb, int ms) {
    int i = blockIdx.x * blockDim.x + threadIdx.x;
    if (i <= mb) g_tb[0][i] = make_float4(0.f, 0.f, 0.f, 0.f);
    if (i <= ms) g_ts[0][i] = make_float4(0.f, 0.f, 0.f, 0.f);
}

__global__ void __launch_bounds__(256) splat(
        const int* __restrict__ osb, const float* __restrict__ wsb,
        const int* __restrict__ oss, const float* __restrict__ wss,
        int use_ones) {
    int n = blockIdx.x * blockDim.x + threadIdx.x;
    if (n >= NPIX) return;
    float4 q = use_ones ? make_float4(1.f, 1.f, 1.f, 1.f) : g_Q[n];
#pragma unroll
    for (int r = 0; r < D1B; r++) {
        int o = osb[n * D1B + r];
        float w = wsb[n * D1B + r];
        red4(&g_tb[0][o], q.x * w, q.y * w, q.z * w, q.w * w);
    }
#pragma unroll
    for (int r = 0; r < D1S; r++) {
        int o = oss[n * D1S + r];
        float w = wss[n * D1S + r];
        red4(&g_ts[0][o], q.x * w, q.y * w, q.z * w, q.w * w);
    }
}

// One blur pass: dst[m+1] = src[m+1] + 0.5*(src[n1]+src[n2]); dst[0]=0 (missing slot).
// Handles bilateral rows [0,Mb) and (when Ms>0) spatial rows [Mb, Mb+Ms) in one launch.
__global__ void __launch_bounds__(256) blur_pass(
        const int2* __restrict__ bnb, int Mb, int sb,
        const int2* __restrict__ bns, int Ms, int ss) {
    int t = blockIdx.x * blockDim.x + threadIdx.x;
    if (t < Mb) {
        const float4* __restrict__ src = g_tb[sb];
        float4* __restrict__ dst = g_tb[sb ^ 1];
        int2 nb = bnb[t];
        float4 c = src[t + 1];
        float4 a = src[nb.x];
        float4 b = src[nb.y];
        dst[t + 1] = make_float4(c.x + 0.5f * (a.x + b.x),
                                 c.y + 0.5f * (a.y + b.y),
                                 c.z + 0.5f * (a.z + b.z),
                                 c.w + 0.5f * (a.w + b.w));
        if (t == 0) dst[0] = make_float4(0.f, 0.f, 0.f, 0.f);
    } else {
        int m = t - Mb;
        if (m < Ms) {
            const float4* __restrict__ src = g_ts[ss];
            float4* __restrict__ dst = g_ts[ss ^ 1];
            int2 nb = bns[m];
            float4 c = src[m + 1];
            float4 a = src[nb.x];
            float4 b = src[nb.y];
            dst[m + 1] = make_float4(c.x + 0.5f * (a.x + b.x),
                                     c.y + 0.5f * (a.y + b.y),
                                     c.z + 0.5f * (a.z + b.z),
                                     c.w + 0.5f * (a.w + b.w));
            if (m == 0) dst[0] = make_float4(0.f, 0.f, 0.f, 0.f);
        }
    }
}

// Slice the ones-filter result -> per-pixel inverse norms.
__global__ void __launch_bounds__(256) norm_slice(
        const int* __restrict__ osb, const float* __restrict__ wsb,
        const int* __restrict__ oss, const float* __restrict__ wss,
        int tb, int ts) {
    int n = blockIdx.x * blockDim.x + threadIdx.x;
    if (n >= NPIX) return;
    float sb = 0.f;
#pragma unroll
    for (int r = 0; r < D1B; r++)
        sb += g_tb[tb][osb[n * D1B + r]].x * wsb[n * D1B + r];
    g_inb[n] = 1.0f / (ALPHA_B * sb + 1e-20f);
    float ssum = 0.f;
#pragma unroll
    for (int r = 0; r < D1S; r++)
        ssum += g_ts[ts][oss[n * D1S + r]].x * wss[n * D1S + r];
    g_ins[n] = 1.0f / (ALPHA_S * ssum + 1e-20f);
}

// Slice both lattices, form message, apply mean-field softmax update.
__global__ void __launch_bounds__(256) slice_mf(
        const float4* __restrict__ unary,
        const int* __restrict__ osb, const float* __restrict__ wsb,
        const int* __restrict__ oss, const float* __restrict__ wss,
        int tb, int ts,
        float4* __restrict__ outp, int write_out) {
    int n = blockIdx.x * blockDim.x + threadIdx.x;
    if (n >= NPIX) return;
    float4 fb = make_float4(0.f, 0.f, 0.f, 0.f);
#pragma unroll
    for (int r = 0; r < D1B; r++) {
        int o = osb[n * D1B + r];
        float w = wsb[n * D1B + r];
        float4 v = g_tb[tb][o];
        fb.x += v.x * w; fb.y += v.y * w; fb.z += v.z * w; fb.w += v.w * w;
    }
    float4 fs = make_float4(0.f, 0.f, 0.f, 0.f);
#pragma unroll
    for (int r = 0; r < D1S; r++) {
        int o = oss[n * D1S + r];
        float w = wss[n * D1S + r];
        float4 v = g_ts[ts][o];
        fs.x += v.x * w; fs.y += v.y * w; fs.z += v.z * w; fs.w += v.w * w;
    }
    float cb = BI_COMPAT * ALPHA_B * g_inb[n];
    float cs = SP_COMPAT * ALPHA_S * g_ins[n];
    float4 msg = make_float4(fb.x * cb + fs.x * cs,
                             fb.y * cb + fs.y * cs,
                             fb.z * cb + fs.z * cs,
                             fb.w * cb + fs.w * cs);
    float4 q = softmax_neg(unary[n], msg);
    if (write_out) outp[n] = q;
    else           g_Q[n] = q;
}

extern "C" void kernel_launch(void* const* d_in, const int* in_sizes, int n_in,
                              void* d_out, int out_size) {
    const float4* unary = (const float4*)d_in[0];
    const float*  wsb   = (const float*)d_in[1];
    const int*    osb   = (const int*)d_in[2];
    const int2*   bnb   = (const int2*)d_in[3];
    const float*  wss   = (const float*)d_in[5];
    const int*    oss   = (const int*)d_in[6];
    const int2*   bns   = (const int2*)d_in[7];

    int Mb = in_sizes[3] / (D1B * 2);   // blur_neighbors_bilateral: [6, Mb, 2]
    int Ms = in_sizes[7] / (D1S * 2);   // blur_neighbors_spatial:   [3, Ms, 2]

    const int TPB = 256;
    const int nblk = (NPIX + TPB - 1) / TPB;
    int maxM = (Mb > Ms ? Mb : Ms);
    const int zblk = (maxM + 1 + TPB - 1) / TPB;

    // ---- Prologue: Q0 = softmax(-u); norms via ones-filter ----
    init_q<<<nblk, TPB>>>(unary);
    zero_tables<<<zblk, TPB>>>(Mb, Ms);
    splat<<<nblk, TPB>>>(osb, wsb, oss, wss, 1);
    for (int j = 0; j < D1B; j++) {
        int ms = (j < D1S) ? Ms : 0;
        int tot = Mb + ms;
        blur_pass<<<(tot + TPB - 1) / TPB, TPB>>>(
            bnb + (size_t)j * Mb, Mb, j & 1,
            bns + (size_t)(j < D1S ? j : 0) * Ms, ms, j & 1);
    }
    // bilateral result in buffer 0 (6 passes), spatial in buffer 1 (3 passes)
    norm_slice<<<nblk, TPB>>>(osb, wsb, oss, wss, 0, 1);

    // ---- 10 mean-field iterations ----
    for (int it = 0; it < 10; it++) {
        zero_tables<<<zblk, TPB>>>(Mb, Ms);
        splat<<<nblk, TPB>>>(osb, wsb, oss, wss, 0);
        for (int j = 0; j < D1B; j++) {
            int ms = (j < D1S) ? Ms : 0;
            int tot = Mb + ms;
            blur_pass<<<(tot + TPB - 1) / TPB, TPB>>>(
                bnb + (size_t)j * Mb, Mb, j & 1,
                bns + (size_t)(j < D1S ? j : 0) * Ms, ms, j & 1);
        }
        slice_mf<<<nblk, TPB>>>(unary, osb, wsb, oss, wss, 0, 1,
                                (float4*)d_out, it == 9 ? 1 : 0);
    }
}

// round 3
// speedup vs baseline: 1.0717x; 1.0717x over previous
#include <cuda_runtime.h>

#define NPIX (512*512)
#define D1B 6
#define D1S 3
#define MAXMB (D1B*NPIX+1)
#define MAXMS (D1S*NPIX+1)
#define ALPHA_B (32.0f/33.0f)
#define ALPHA_S 0.8f
#define BI_COMPAT 10.0f
#define SP_COMPAT 3.0f
#define TPB 256

// Tables: 3-buffer ping-pong per lattice. Scratch via device globals (no allocs allowed).
__device__ float4 g_tb[3][MAXMB];
__device__ float4 g_ts[3][MAXMS];
// Composed 2-pass neighbor indices: bilateral pairs (0,1),(2,3),(4,5); spatial pair (0,1).
__device__ int    g_cb[3][(size_t)(MAXMB - 1) * 8];
__device__ int    g_cs9[(size_t)(MAXMS - 1) * 8];
__device__ float4 g_Q[NPIX];
__device__ float  g_inb[NPIX];
__device__ float  g_ins[NPIX];

__device__ __forceinline__ void red4(float4* p, float x, float y, float z, float w) {
    asm volatile("red.global.add.v4.f32 [%0], {%1,%2,%3,%4};"
                 :: "l"(p), "f"(x), "f"(y), "f"(z), "f"(w) : "memory");
}

__device__ __forceinline__ float4 softmax_neg(float4 u, float4 msg) {
    float zx = msg.x - u.x, zy = msg.y - u.y, zz = msg.z - u.z, zw = msg.w - u.w;
    float m = fmaxf(fmaxf(zx, zy), fmaxf(zz, zw));
    float ex = __expf(zx - m), ey = __expf(zy - m), ez = __expf(zz - m), ew = __expf(zw - m);
    float inv = 1.0f / (ex + ey + ez + ew);
    return make_float4(ex * inv, ey * inv, ez * inv, ew * inv);
}

// Build composed 2-pass stencils.
// t1[k]   = t0[k] + .5(t0[A]+t0[B]),   (A,B)=bn[j1][k-1], t1[0]=0
// t2[m+1] = t1[m+1] + .5(t1[N1]+t1[N2]), (N1,N2)=bn[j2][m]
// => 9-term stencil over t0: center(1), A,B(.5), N1(.5), its children(.25), N2(.5), children(.25).
// Index 0 always reads table[0]==0, so "missing" needs no masking; a missing N kills its children.
__global__ void __launch_bounds__(TPB) compose(const int2* __restrict__ bnb, int Mb,
                                               const int2* __restrict__ bns, int Ms) {
    int t = blockIdx.x * blockDim.x + threadIdx.x;
    if (t < Mb) {
#pragma unroll
        for (int p = 0; p < 3; p++) {
            const int2* r1 = bnb + (size_t)(2 * p) * Mb;
            const int2* r2 = bnb + (size_t)(2 * p + 1) * Mb;
            int2 ab = r1[t];
            int2 nn = r2[t];
            int o3 = 0, o4 = 0, o6 = 0, o7 = 0;
            if (nn.x > 0) { int2 c = r1[nn.x - 1]; o3 = c.x; o4 = c.y; }
            if (nn.y > 0) { int2 c = r1[nn.y - 1]; o6 = c.x; o7 = c.y; }
            int4* dst = (int4*)&g_cb[p][(size_t)t * 8];
            dst[0] = make_int4(ab.x, ab.y, nn.x, o3);
            dst[1] = make_int4(o4, nn.y, o6, o7);
        }
    } else {
        int m = t - Mb;
        if (m < Ms) {
            const int2* r1 = bns;
            const int2* r2 = bns + (size_t)Ms;
            int2 ab = r1[m];
            int2 nn = r2[m];
            int o3 = 0, o4 = 0, o6 = 0, o7 = 0;
            if (nn.x > 0) { int2 c = r1[nn.x - 1]; o3 = c.x; o4 = c.y; }
            if (nn.y > 0) { int2 c = r1[nn.y - 1]; o6 = c.x; o7 = c.y; }
            int4* dst = (int4*)&g_cs9[(size_t)m * 8];
            dst[0] = make_int4(ab.x, ab.y, nn.x, o3);
            dst[1] = make_int4(o4, nn.y, o6, o7);
        }
    }
}

__device__ __forceinline__ float4 gather9(const int* __restrict__ idx8,
                                          const float4* __restrict__ s, int center) {
    int4 i0 = *(const int4*)(idx8);
    int4 i1 = *(const int4*)(idx8 + 4);
    float4 c  = s[center];
    float4 a0 = s[i0.x], a1 = s[i0.y];
    float4 n1 = s[i0.z], n1a = s[i0.w], n1b = s[i1.x];
    float4 n2 = s[i1.y], n2a = s[i1.z], n2b = s[i1.w];
    float4 r;
    r.x = c.x + 0.5f * (a0.x + a1.x + n1.x + n2.x) + 0.25f * (n1a.x + n1b.x + n2a.x + n2b.x);
    r.y = c.y + 0.5f * (a0.y + a1.y + n1.y + n2.y) + 0.25f * (n1a.y + n1b.y + n2a.y + n2b.y);
    r.z = c.z + 0.5f * (a0.z + a1.z + n1.z + n2.z) + 0.25f * (n1a.z + n1b.z + n2a.z + n2b.z);
    r.w = c.w + 0.5f * (a0.w + a1.w + n1.w + n2.w) + 0.25f * (n1a.w + n1b.w + n2a.w + n2b.w);
    return r;
}

__global__ void __launch_bounds__(TPB) splat(
        const int* __restrict__ osb, const float* __restrict__ wsb,
        const int* __restrict__ oss, const float* __restrict__ wss,
        int use_ones) {
    int n = blockIdx.x * blockDim.x + threadIdx.x;
    if (n >= NPIX) return;
    float4 q = use_ones ? make_float4(1.f, 1.f, 1.f, 1.f) : g_Q[n];
#pragma unroll
    for (int r = 0; r < D1B; r++) {
        int o = osb[n * D1B + r];
        float w = wsb[n * D1B + r];
        red4(&g_tb[0][o], q.x * w, q.y * w, q.z * w, q.w * w);
    }
#pragma unroll
    for (int r = 0; r < D1S; r++) {
        int o = oss[n * D1S + r];
        float w = wss[n * D1S + r];
        red4(&g_ts[0][o], q.x * w, q.y * w, q.z * w, q.w * w);
    }
}

// K1: bilateral fused passes (0,1): tb0->tb1 ; spatial fused passes (0,1): ts0->ts1
__global__ void __launch_bounds__(TPB) k1(int Mb, int Ms) {
    int t = blockIdx.x * blockDim.x + threadIdx.x;
    if (t < Mb) {
        g_tb[1][t + 1] = gather9(&g_cb[0][(size_t)t * 8], g_tb[0], t + 1);
        if (t == 0) g_tb[1][0] = make_float4(0.f, 0.f, 0.f, 0.f);
    } else {
        int m = t - Mb;
        if (m < Ms) {
            g_ts[1][m + 1] = gather9(&g_cs9[(size_t)m * 8], g_ts[0], m + 1);
            if (m == 0) g_ts[1][0] = make_float4(0.f, 0.f, 0.f, 0.f);
        }
    }
}

// K2: bilateral fused passes (2,3): tb1->tb2 ; spatial simple pass 2: ts1->ts2
__global__ void __launch_bounds__(TPB) k2(int Mb, const int2* __restrict__ bns, int Ms) {
    int t = blockIdx.x * blockDim.x + threadIdx.x;
    if (t < Mb) {
        g_tb[2][t + 1] = gather9(&g_cb[1][(size_t)t * 8], g_tb[1], t + 1);
        if (t == 0) g_tb[2][0] = make_float4(0.f, 0.f, 0.f, 0.f);
    } else {
        int m = t - Mb;
        if (m < Ms) {
            int2 nb = bns[(size_t)2 * Ms + m];
            const float4* __restrict__ s = g_ts[1];
            float4 c = s[m + 1], a = s[nb.x], b = s[nb.y];
            g_ts[2][m + 1] = make_float4(c.x + 0.5f * (a.x + b.x), c.y + 0.5f * (a.y + b.y),
                                         c.z + 0.5f * (a.z + b.z), c.w + 0.5f * (a.w + b.w));
            if (m == 0) g_ts[2][0] = make_float4(0.f, 0.f, 0.f, 0.f);
        }
    }
}

// K3: bilateral fused passes (4,5): tb2->tb1
__global__ void __launch_bounds__(TPB) k3(int Mb) {
    int t = blockIdx.x * blockDim.x + threadIdx.x;
    if (t >= Mb) return;
    g_tb[1][t + 1] = gather9(&g_cb[2][(size_t)t * 8], g_tb[2], t + 1);
    if (t == 0) g_tb[1][0] = make_float4(0.f, 0.f, 0.f, 0.f);
}

// Prologue slice: norms from ones-filter (tb1, ts2), init Q, zero splat buffers.
__global__ void __launch_bounds__(TPB) norm_slice_init(
        const float4* __restrict__ unary,
        const int* __restrict__ osb, const float* __restrict__ wsb,
        const int* __restrict__ oss, const float* __restrict__ wss,
        int Mb, int Ms) {
    int n = blockIdx.x * blockDim.x + threadIdx.x;
    int stride = gridDim.x * blockDim.x;
    if (n < NPIX) {
        float sb = 0.f;
#pragma unroll
        for (int r = 0; r < D1B; r++)
            sb += g_tb[1][osb[n * D1B + r]].x * wsb[n * D1B + r];
        g_inb[n] = 1.0f / (ALPHA_B * sb + 1e-20f);
        float ss = 0.f;
#pragma unroll
        for (int r = 0; r < D1S; r++)
            ss += g_ts[2][oss[n * D1S + r]].x * wss[n * D1S + r];
        g_ins[n] = 1.0f / (ALPHA_S * ss + 1e-20f);
        g_Q[n] = softmax_neg(unary[n], make_float4(0.f, 0.f, 0.f, 0.f));
    }
    for (int i = n; i <= Mb; i += stride) g_tb[0][i] = make_float4(0.f, 0.f, 0.f, 0.f);
    for (int i = n; i <= Ms; i += stride) g_ts[0][i] = make_float4(0.f, 0.f, 0.f, 0.f);
}

// Iteration slice: message from (tb1, ts2), softmax update, zero splat buffers.
__global__ void __launch_bounds__(TPB) slice_mf(
        const float4* __restrict__ unary,
        const int* __restrict__ osb, const float* __restrict__ wsb,
        const int* __restrict__ oss, const float* __restrict__ wss,
        float4* __restrict__ outp, int write_out, int Mb, int Ms) {
    int n = blockIdx.x * blockDim.x + threadIdx.x;
    int stride = gridDim.x * blockDim.x;
    if (n < NPIX) {
        float4 fb = make_float4(0.f, 0.f, 0.f, 0.f);
#pragma unroll
        for (int r = 0; r < D1B; r++) {
            int o = osb[n * D1B + r];
            float w = wsb[n * D1B + r];
            float4 v = g_tb[1][o];
            fb.x += v.x * w; fb.y += v.y * w; fb.z += v.z * w; fb.w += v.w * w;
        }
        float4 fs = make_float4(0.f, 0.f, 0.f, 0.f);
#pragma unroll
        for (int r = 0; r < D1S; r++) {
            int o = oss[n * D1S + r];
            float w = wss[n * D1S + r];
            float4 v = g_ts[2][o];
            fs.x += v.x * w; fs.y += v.y * w; fs.z += v.z * w; fs.w += v.w * w;
        }
        float cb = BI_COMPAT * ALPHA_B * g_inb[n];
        float cs = SP_COMPAT * ALPHA_S * g_ins[n];
        float4 msg = make_float4(fb.x * cb + fs.x * cs, fb.y * cb + fs.y * cs,
                                 fb.z * cb + fs.z * cs, fb.w * cb + fs.w * cs);
        float4 q = softmax_neg(unary[n], msg);
        if (write_out) outp[n] = q;
        else           g_Q[n] = q;
    }
    for (int i = n; i <= Mb; i += stride) g_tb[0][i] = make_float4(0.f, 0.f, 0.f, 0.f);
    for (int i = n; i <= Ms; i += stride) g_ts[0][i] = make_float4(0.f, 0.f, 0.f, 0.f);
}

extern "C" void kernel_launch(void* const* d_in, const int* in_sizes, int n_in,
                              void* d_out, int out_size) {
    const float4* unary = (const float4*)d_in[0];
    const float*  wsb   = (const float*)d_in[1];
    const int*    osb   = (const int*)d_in[2];
    const int2*   bnb   = (const int2*)d_in[3];
    const float*  wss   = (const float*)d_in[5];
    const int*    oss   = (const int*)d_in[6];
    const int2*   bns   = (const int2*)d_in[7];

    int Mb = in_sizes[3] / (D1B * 2);   // blur_neighbors_bilateral: [6, Mb, 2]
    int Ms = in_sizes[7] / (D1S * 2);   // blur_neighbors_spatial:   [3, Ms, 2]

    const int nblk = (NPIX + TPB - 1) / TPB;
    const int cblk = (Mb + Ms + TPB - 1) / TPB;
    const int bblk = (Mb + TPB - 1) / TPB;

    // ---- Prologue ----
    // Splat buffers (tb0/ts0) are zero: module-load init on first call, the final
    // slice_mf's zeroing on every subsequent call/replay.
    compose<<<cblk, TPB>>>(bnb, Mb, bns, Ms);
    splat<<<nblk, TPB>>>(osb, wsb, oss, wss, 1);
    k1<<<cblk, TPB>>>(Mb, Ms);
    k2<<<cblk, TPB>>>(Mb, bns, Ms);
    k3<<<bblk, TPB>>>(Mb);
    norm_slice_init<<<nblk, TPB>>>(unary, osb, wsb, oss, wss, Mb, Ms);

    // ---- 10 mean-field iterations ----
    for (int it = 0; it < 10; it++) {
        splat<<<nblk, TPB>>>(osb, wsb, oss, wss, 0);
        k1<<<cblk, TPB>>>(Mb, Ms);
        k2<<<cblk, TPB>>>(Mb, bns, Ms);
        k3<<<bblk, TPB>>>(Mb);
        slice_mf<<<nblk, TPB>>>(unary, osb, wsb, oss, wss,
                                (float4*)d_out, it == 9 ? 1 : 0, Mb, Ms);
    }
}

// round 4
// speedup vs baseline: 1.1903x; 1.1107x over previous
#include <cuda_runtime.h>

#define NPIX (512*512)
#define D1B 6
#define D1S 3
#define MAXMB (D1B*NPIX+1)
#define MAXMS (D1S*NPIX+1)
#define ALPHA_B (32.0f/33.0f)
#define ALPHA_S 0.8f
#define BI_COMPAT 10.0f
#define SP_COMPAT 3.0f
#define TPB 256

// Tables: 3-buffer ping-pong per lattice. Scratch via device globals (no allocs allowed).
__device__ float4 g_tb[3][MAXMB];
__device__ float4 g_ts[3][MAXMS];
// Composed 2-pass neighbor indices: bilateral pairs (0,1),(2,3),(4,5); spatial pair (0,1).
__device__ int    g_cb[3][(size_t)(MAXMB - 1) * 8];
__device__ int    g_cs9[(size_t)(MAXMS - 1) * 8];
__device__ float  g_inb[NPIX];
__device__ float  g_ins[NPIX];

__device__ __forceinline__ void red4(float4* p, float x, float y, float z, float w) {
    asm volatile("red.global.add.v4.f32 [%0], {%1,%2,%3,%4};"
                 :: "l"(p), "f"(x), "f"(y), "f"(z), "f"(w) : "memory");
}

__device__ __forceinline__ float4 softmax_neg(float4 u, float4 msg) {
    float zx = msg.x - u.x, zy = msg.y - u.y, zz = msg.z - u.z, zw = msg.w - u.w;
    float m = fmaxf(fmaxf(zx, zy), fmaxf(zz, zw));
    float ex = __expf(zx - m), ey = __expf(zy - m), ez = __expf(zz - m), ew = __expf(zw - m);
    float inv = 1.0f / (ex + ey + ez + ew);
    return make_float4(ex * inv, ey * inv, ez * inv, ew * inv);
}

// Build composed 2-pass stencils (see R3 derivation). Index 0 reads table[0]==0,
// so missing neighbors need no masking; a missing mid-node kills its children.
__global__ void __launch_bounds__(TPB) compose(const int2* __restrict__ bnb, int Mb,
                                               const int2* __restrict__ bns, int Ms) {
    int t = blockIdx.x * blockDim.x + threadIdx.x;
    if (t < Mb) {
#pragma unroll
        for (int p = 0; p < 3; p++) {
            const int2* r1 = bnb + (size_t)(2 * p) * Mb;
            const int2* r2 = bnb + (size_t)(2 * p + 1) * Mb;
            int2 ab = r1[t];
            int2 nn = r2[t];
            int o3 = 0, o4 = 0, o6 = 0, o7 = 0;
            if (nn.x > 0) { int2 c = r1[nn.x - 1]; o3 = c.x; o4 = c.y; }
            if (nn.y > 0) { int2 c = r1[nn.y - 1]; o6 = c.x; o7 = c.y; }
            int4* dst = (int4*)&g_cb[p][(size_t)t * 8];
            dst[0] = make_int4(ab.x, ab.y, nn.x, o3);
            dst[1] = make_int4(o4, nn.y, o6, o7);
        }
    } else {
        int m = t - Mb;
        if (m < Ms) {
            const int2* r1 = bns;
            const int2* r2 = bns + (size_t)Ms;
            int2 ab = r1[m];
            int2 nn = r2[m];
            int o3 = 0, o4 = 0, o6 = 0, o7 = 0;
            if (nn.x > 0) { int2 c = r1[nn.x - 1]; o3 = c.x; o4 = c.y; }
            if (nn.y > 0) { int2 c = r1[nn.y - 1]; o6 = c.x; o7 = c.y; }
            int4* dst = (int4*)&g_cs9[(size_t)m * 8];
            dst[0] = make_int4(ab.x, ab.y, nn.x, o3);
            dst[1] = make_int4(o4, nn.y, o6, o7);
        }
    }
}

__device__ __forceinline__ float4 gather9(const int* __restrict__ idx8,
                                          const float4* __restrict__ s, int center) {
    int4 i0 = *(const int4*)(idx8);
    int4 i1 = *(const int4*)(idx8 + 4);
    float4 c  = s[center];
    float4 a0 = s[i0.x], a1 = s[i0.y];
    float4 n1 = s[i0.z], n1a = s[i0.w], n1b = s[i1.x];
    float4 n2 = s[i1.y], n2a = s[i1.z], n2b = s[i1.w];
    float4 r;
    r.x = c.x + 0.5f * (a0.x + a1.x + n1.x + n2.x) + 0.25f * (n1a.x + n1b.x + n2a.x + n2b.x);
    r.y = c.y + 0.5f * (a0.y + a1.y + n1.y + n2.y) + 0.25f * (n1a.y + n1b.y + n2a.y + n2b.y);
    r.z = c.z + 0.5f * (a0.z + a1.z + n1.z + n2.z) + 0.25f * (n1a.z + n1b.z + n2a.z + n2b.z);
    r.w = c.w + 0.5f * (a0.w + a1.w + n1.w + n2.w) + 0.25f * (n1a.w + n1b.w + n2a.w + n2b.w);
    return r;
}

// Prologue-only: splat ones into tb0/ts0 (must be zero at entry; guaranteed by
// static init on first call, and by the epilogue of every full launch after).
__global__ void __launch_bounds__(TPB) splat_ones(
        const int* __restrict__ osb, const float* __restrict__ wsb,
        const int* __restrict__ oss, const float* __restrict__ wss) {
    int n = blockIdx.x * blockDim.x + threadIdx.x;
    if (n >= NPIX) return;
#pragma unroll
    for (int r = 0; r < D1B; r++) {
        int o = osb[n * D1B + r];
        float w = wsb[n * D1B + r];
        red4(&g_tb[0][o], w, w, w, w);
    }
#pragma unroll
    for (int r = 0; r < D1S; r++) {
        int o = oss[n * D1S + r];
        float w = wss[n * D1S + r];
        red4(&g_ts[0][o], w, w, w, w);
    }
}

// K1: bilateral fused passes (0,1): tb0->tb1 ; spatial fused passes (0,1): ts0->ts1
__global__ void __launch_bounds__(TPB) k1(int Mb, int Ms) {
    int t = blockIdx.x * blockDim.x + threadIdx.x;
    if (t < Mb) {
        g_tb[1][t + 1] = gather9(&g_cb[0][(size_t)t * 8], g_tb[0], t + 1);
        if (t == 0) g_tb[1][0] = make_float4(0.f, 0.f, 0.f, 0.f);
    } else {
        int m = t - Mb;
        if (m < Ms) {
            g_ts[1][m + 1] = gather9(&g_cs9[(size_t)m * 8], g_ts[0], m + 1);
            if (m == 0) g_ts[1][0] = make_float4(0.f, 0.f, 0.f, 0.f);
        }
    }
}

// K2: bilateral fused passes (2,3): tb1->tb2 ; spatial simple pass 2: ts1->ts2.
// Also zeros tb0/ts0 (dead after k1) for the upcoming fused slice+splat.
__global__ void __launch_bounds__(TPB) k2(int Mb, const int2* __restrict__ bns, int Ms) {
    int t = blockIdx.x * blockDim.x + threadIdx.x;
    if (t < Mb) {
        g_tb[2][t + 1] = gather9(&g_cb[1][(size_t)t * 8], g_tb[1], t + 1);
        g_tb[0][t + 1] = make_float4(0.f, 0.f, 0.f, 0.f);
        if (t == 0) {
            g_tb[2][0] = make_float4(0.f, 0.f, 0.f, 0.f);
            g_tb[0][0] = make_float4(0.f, 0.f, 0.f, 0.f);
        }
    } else {
        int m = t - Mb;
        if (m < Ms) {
            int2 nb = bns[(size_t)2 * Ms + m];
            const float4* __restrict__ s = g_ts[1];
            float4 c = s[m + 1], a = s[nb.x], b = s[nb.y];
            g_ts[2][m + 1] = make_float4(c.x + 0.5f * (a.x + b.x), c.y + 0.5f * (a.y + b.y),
                                         c.z + 0.5f * (a.z + b.z), c.w + 0.5f * (a.w + b.w));
            g_ts[0][m + 1] = make_float4(0.f, 0.f, 0.f, 0.f);
            if (m == 0) {
                g_ts[2][0] = make_float4(0.f, 0.f, 0.f, 0.f);
                g_ts[0][0] = make_float4(0.f, 0.f, 0.f, 0.f);
            }
        }
    }
}

// K3: bilateral fused passes (4,5): tb2->tb1
__global__ void __launch_bounds__(TPB) k3(int Mb) {
    int t = blockIdx.x * blockDim.x + threadIdx.x;
    if (t >= Mb) return;
    g_tb[1][t + 1] = gather9(&g_cb[2][(size_t)t * 8], g_tb[2], t + 1);
    if (t == 0) g_tb[1][0] = make_float4(0.f, 0.f, 0.f, 0.f);
}

__device__ __forceinline__ void splat_q(
        float4 q,
        const int* __restrict__ osb, const float* __restrict__ wsb,
        const int* __restrict__ oss, const float* __restrict__ wss, int n) {
#pragma unroll
    for (int r = 0; r < D1B; r++) {
        int o = osb[n * D1B + r];
        float w = wsb[n * D1B + r];
        red4(&g_tb[0][o], q.x * w, q.y * w, q.z * w, q.w * w);
    }
#pragma unroll
    for (int r = 0; r < D1S; r++) {
        int o = oss[n * D1S + r];
        float w = wss[n * D1S + r];
        red4(&g_ts[0][o], q.x * w, q.y * w, q.z * w, q.w * w);
    }
}

// Prologue slice: norms from ones-filter (tb1/ts2), Q0 = softmax(-u), splat Q0.
__global__ void __launch_bounds__(TPB) norm_slice_init(
        const float4* __restrict__ unary,
        const int* __restrict__ osb, const float* __restrict__ wsb,
        const int* __restrict__ oss, const float* __restrict__ wss) {
    int n = blockIdx.x * blockDim.x + threadIdx.x;
    if (n >= NPIX) return;
    float sb = 0.f;
#pragma unroll
    for (int r = 0; r < D1B; r++)
        sb += g_tb[1][osb[n * D1B + r]].x * wsb[n * D1B + r];
    g_inb[n] = 1.0f / (ALPHA_B * sb + 1e-20f);
    float ss = 0.f;
#pragma unroll
    for (int r = 0; r < D1S; r++)
        ss += g_ts[2][oss[n * D1S + r]].x * wss[n * D1S + r];
    g_ins[n] = 1.0f / (ALPHA_S * ss + 1e-20f);
    float4 q = softmax_neg(unary[n], make_float4(0.f, 0.f, 0.f, 0.f));
    splat_q(q, osb, wsb, oss, wss, n);
}

// Fused slice + mean-field update + splat of the new Q (or d_out write on last iter).
__global__ void __launch_bounds__(TPB) slice_mf(
        const float4* __restrict__ unary,
        const int* __restrict__ osb, const float* __restrict__ wsb,
        const int* __restrict__ oss, const float* __restrict__ wss,
        float4* __restrict__ outp, int write_out) {
    int n = blockIdx.x * blockDim.x + threadIdx.x;
    if (n >= NPIX) return;
    float4 fb = make_float4(0.f, 0.f, 0.f, 0.f);
    int   ob[D1B];
    float wb[D1B];
#pragma unroll
    for (int r = 0; r < D1B; r++) {
        ob[r] = osb[n * D1B + r];
        wb[r] = wsb[n * D1B + r];
        float4 v = g_tb[1][ob[r]];
        fb.x += v.x * wb[r]; fb.y += v.y * wb[r]; fb.z += v.z * wb[r]; fb.w += v.w * wb[r];
    }
    float4 fs = make_float4(0.f, 0.f, 0.f, 0.f);
    int   osr[D1S];
    float wsr[D1S];
#pragma unroll
    for (int r = 0; r < D1S; r++) {
        osr[r] = oss[n * D1S + r];
        wsr[r] = wss[n * D1S + r];
        float4 v = g_ts[2][osr[r]];
        fs.x += v.x * wsr[r]; fs.y += v.y * wsr[r]; fs.z += v.z * wsr[r]; fs.w += v.w * wsr[r];
    }
    float cb = BI_COMPAT * ALPHA_B * g_inb[n];
    float cs = SP_COMPAT * ALPHA_S * g_ins[n];
    float4 msg = make_float4(fb.x * cb + fs.x * cs, fb.y * cb + fs.y * cs,
                             fb.z * cb + fs.z * cs, fb.w * cb + fs.w * cs);
    float4 q = softmax_neg(unary[n], msg);
    if (write_out) {
        outp[n] = q;   // final iteration: no splat, tables stay zeroed for next launch
    } else {
#pragma unroll
        for (int r = 0; r < D1B; r++)
            red4(&g_tb[0][ob[r]], q.x * wb[r], q.y * wb[r], q.z * wb[r], q.w * wb[r]);
#pragma unroll
        for (int r = 0; r < D1S; r++)
            red4(&g_ts[0][osr[r]], q.x * wsr[r], q.y * wsr[r], q.z * wsr[r], q.w * wsr[r]);
    }
}

extern "C" void kernel_launch(void* const* d_in, const int* in_sizes, int n_in,
                              void* d_out, int out_size) {
    const float4* unary = (const float4*)d_in[0];
    const float*  wsb   = (const float*)d_in[1];
    const int*    osb   = (const int*)d_in[2];
    const int2*   bnb   = (const int2*)d_in[3];
    const float*  wss   = (const float*)d_in[5];
    const int*    oss   = (const int*)d_in[6];
    const int2*   bns   = (const int2*)d_in[7];

    int Mb = in_sizes[3] / (D1B * 2);   // blur_neighbors_bilateral: [6, Mb, 2]
    int Ms = in_sizes[7] / (D1S * 2);   // blur_neighbors_spatial:   [3, Ms, 2]

    const int nblk = (NPIX + TPB - 1) / TPB;
    const int cblk = (Mb + Ms + TPB - 1) / TPB;
    const int bblk = (Mb + TPB - 1) / TPB;

    // ---- Prologue: ones-filter for norms, Q0 init + splat ----
    compose<<<cblk, TPB>>>(bnb, Mb, bns, Ms);
    splat_ones<<<nblk, TPB>>>(osb, wsb, oss, wss);
    k1<<<cblk, TPB>>>(Mb, Ms);
    k2<<<cblk, TPB>>>(Mb, bns, Ms);
    k3<<<bblk, TPB>>>(Mb);
    norm_slice_init<<<nblk, TPB>>>(unary, osb, wsb, oss, wss);

    // ---- 10 mean-field iterations (splat fused into previous slice) ----
    for (int it = 0; it < 10; it++) {
        k1<<<cblk, TPB>>>(Mb, Ms);
        k2<<<cblk, TPB>>>(Mb, bns, Ms);
        k3<<<bblk, TPB>>>(Mb);
        slice_mf<<<nblk, TPB>>>(unary, osb, wsb, oss, wss,
                                (float4*)d_out, it == 9 ? 1 : 0);
    }
}